// round 16
// baseline (speedup 1.0000x reference)
#include <cuda_runtime.h>
#include <cuda_fp16.h>
#include <cstdint>
#include <cstddef>

// Biaffine: out[b,x,y,o] = sum_ij in1[b,x,i] w1[i,o,j] in2[b,y,j] + p + q + bias
//   stage1: U' = in1_hi @ w1_hi^T (+ w2b^T folded -> q) ; p-tile = in1 @ w2a
//   stage2: out = U' @ in2_hi^T + (p + bias)
// Both stages fused into ONE kernel with per-m-tile dependency counters:
// grid = 16 groups x (513 stage1 CTAs + 256 stage2 CTAs); stage2 CTAs spin on
// g_cnt[mt]==513 (release: threadfence+atomicAdd; acquire: volatile+fence).
// mma.sync.m16n8k16 fp16 fp32-acc at the sm_103a SIMT HMMA ceiling.

#define B_ 8
#define L_ 256
#define D_ 512
#define O_ 128
#define NCH 8                   // 512 / 64
#define TBUF 18432              // 128 rows * 144B
#define CBUF (2 * TBUF)         // A + B tiles per chunk buffer
#define SMEM_BYTES 110592       // 3 * CBUF (epilogues fit inside)

using hf = __half;

// -------------------- device globals (no runtime alloc) --------------------
__device__ __align__(128) hf g_Ahi[2048 * 512];
__device__ __align__(128) hf g_I2hi[2048 * 512];
__device__ __align__(128) hf g_Whi[(size_t)65536 * 512];
__device__ __align__(128) hf g_Uhi[(size_t)262144 * 512];
__device__ __align__(128) hf g_W2aT[128 * 512];     // [o][i] fp16 (p-tile B operand)
__device__ __align__(128) float g_W2bT[128 * 512];  // [o][j] fp32 (U epilogue addend)
__device__ __align__(128) float g_p[2048 * 128];
__device__ int g_cnt[16];                           // per-m-tile completion counters

// -------------------- helpers --------------------
__device__ __forceinline__ uint32_t smem_u32(const void* p) {
    uint32_t a;
    asm("{ .reg .u64 t; cvta.to.shared.u64 t, %1; cvt.u32.u64 %0, t; }" : "=r"(a) : "l"(p));
    return a;
}
__device__ __forceinline__ void cpa16(uint32_t s, const void* g) {
    asm volatile("cp.async.cg.shared.global [%0], [%1], 16;" :: "r"(s), "l"(g));
}
#define CP_COMMIT asm volatile("cp.async.commit_group;" ::: "memory")
#define CP_WAIT2  asm volatile("cp.async.wait_group 2;" ::: "memory")
#define CP_WAIT1  asm volatile("cp.async.wait_group 1;" ::: "memory")
#define CP_WAIT0  asm volatile("cp.async.wait_group 0;" ::: "memory")

__device__ __forceinline__ void ldmx4(uint32_t* r, uint32_t addr) {
    asm volatile("ldmatrix.sync.aligned.m8n8.x4.shared.b16 {%0,%1,%2,%3}, [%4];"
                 : "=r"(r[0]), "=r"(r[1]), "=r"(r[2]), "=r"(r[3]) : "r"(addr));
}
__device__ __forceinline__ void mma16816(float* c, const uint32_t* a, uint32_t b0, uint32_t b1) {
    asm("mma.sync.aligned.m16n8k16.row.col.f32.f16.f16.f32 "
        "{%0,%1,%2,%3},{%4,%5,%6,%7},{%8,%9},{%0,%1,%2,%3};"
        : "+f"(c[0]), "+f"(c[1]), "+f"(c[2]), "+f"(c[3])
        : "r"(a[0]), "r"(a[1]), "r"(a[2]), "r"(a[3]), "r"(b0), "r"(b1));
}

// -------------------- chunk loader: A + B tiles 128x64 fp16 (144B stride) ---
__device__ __forceinline__ void load2(uint32_t sbase, int buf,
                                      const hf* __restrict__ ta,
                                      const hf* __restrict__ tb,
                                      int kcol, int t) {
    const int r = t >> 3, c = t & 7;               // r 0..15, c 0..7 (16B units)
    const uint32_t so = sbase + buf * CBUF + r * 144 + c * 16;
    const size_t go = (size_t)r * 512 + kcol + c * 8;
    const hf* ga = ta + go;
    const hf* gb = tb + go;
#pragma unroll
    for (int p = 0; p < 8; p++) cpa16(so + p * (16 * 144), ga + (size_t)16 * p * 512);
#pragma unroll
    for (int p = 0; p < 8; p++) cpa16(so + TBUF + p * (16 * 144), gb + (size_t)16 * p * 512);
}

// -------------------- fragment load + mma --------------------
__device__ __forceinline__ void ld_frags(uint32_t sbase, int buf, int kst,
                                         int wm, int wn, uint32_t lro,
                                         uint32_t ar[4][4], uint32_t br[4][4]) {
    const uint32_t sA = sbase + buf * CBUF + wm * (64 * 144) + lro + kst * 32;
    const uint32_t sB = sbase + buf * CBUF + TBUF + wn * (64 * 144) + lro + kst * 32;
#pragma unroll
    for (int mt = 0; mt < 4; mt++) ldmx4(ar[mt], sA + mt * (16 * 144));
#pragma unroll
    for (int n2 = 0; n2 < 4; n2++) ldmx4(br[n2], sB + n2 * (16 * 144));
}
__device__ __forceinline__ void do_mma(float acc[4][8][4],
                                       uint32_t ar[4][4], uint32_t br[4][4]) {
#pragma unroll
    for (int mt = 0; mt < 4; mt++)
#pragma unroll
        for (int n2 = 0; n2 < 4; n2++) {
            mma16816(acc[mt][n2 * 2 + 0], ar[mt], br[n2][0], br[n2][2]);
            mma16816(acc[mt][n2 * 2 + 1], ar[mt], br[n2][1], br[n2][3]);
        }
}

// -------------------- shared mainloop (CTA 128x128, warps 2x2, 64x64) ------
__device__ __forceinline__ void mma_mainloop(char* smem,
                                             const hf* pa, const hf* pb,
                                             float acc[4][8][4],
                                             int wm, int wn, int lane, int t) {
    const uint32_t sbase = smem_u32(smem);
    const uint32_t lro = (lane & 15) * 144 + (lane >> 4) * 16;

    uint32_t a0[4][4], b0[4][4], a1[4][4], b1[4][4];

    load2(sbase, 0, pa, pb, 0, t);   CP_COMMIT;
    load2(sbase, 1, pa, pb, 64, t);  CP_COMMIT;
    load2(sbase, 2, pa, pb, 128, t); CP_COMMIT;
    CP_WAIT2;                 // buf0 complete
    __syncthreads();
    ld_frags(sbase, 0, 0, wm, wn, lro, a0, b0);

#pragma unroll
    for (int c = 0; c < NCH; c++) {
        const int buf = c % 3;
        ld_frags(sbase, buf, 1, wm, wn, lro, a1, b1);
        do_mma(acc, a0, b0);
        ld_frags(sbase, buf, 2, wm, wn, lro, a0, b0);
        do_mma(acc, a1, b1);
        ld_frags(sbase, buf, 3, wm, wn, lro, a1, b1);
        do_mma(acc, a0, b0);

        if (c + 1 < NCH) {
            if (c == NCH - 2) { CP_WAIT0; } else { CP_WAIT1; }
            __syncthreads();   // all warps done reading buf c
            ld_frags(sbase, (c + 1) % 3, 0, wm, wn, lro, a0, b0);
            do_mma(acc, a1, b1);
            if (c + 3 < NCH) { load2(sbase, (c + 3) % 3, pa, pb, (c + 3) * 64, t); CP_COMMIT; }
        } else {
            do_mma(acc, a1, b1);
        }
    }
}

// -------------------- fused kernel --------------------
// grid: 16 groups * 769 CTAs. Per group g:
//   r in [0,513): stage1, m-tile = g, n-tile by = r (by==512 -> p-tile)
//   r in [513,769): stage2, s = r-513: gx = s>>1 (row in m-tile), n0 = (s&1)*128
__global__ __launch_bounds__(128, 2) void fused_mma(const float* __restrict__ w2,
                                                    float* __restrict__ out) {
    extern __shared__ char smem[];
    const int bid = blockIdx.x;
    const int grp = bid / 769, r = bid % 769;
    const int t = threadIdx.x, lane = t & 31, wid = t >> 5;
    const int wm = wid & 1, wn = wid >> 1;
    const int g = lane >> 2, qp = lane & 3;

    float acc[4][8][4];
#pragma unroll
    for (int i = 0; i < 4; i++)
#pragma unroll
        for (int j = 0; j < 8; j++)
#pragma unroll
            for (int k = 0; k < 4; k++) acc[i][j][k] = 0.f;

    if (r < 513) {
        // ================= stage 1 =================
        const size_t m0 = (size_t)grp * 128;
        const bool ptile = (r == 512);
        const int n0 = ptile ? 0 : r * 128;
        const int o = n0 >> 9, j0 = n0 & 511;

        const hf* pb = ptile ? g_W2aT : (g_Whi + (size_t)n0 * 512);
        mma_mainloop(smem, g_Ahi + m0 * 512, pb, acc, wm, wn, lane, t);

        if (ptile) {
#pragma unroll
            for (int mt = 0; mt < 4; mt++) {
                const int rr = wm * 64 + mt * 16 + g;
#pragma unroll
                for (int nt = 0; nt < 8; nt++) {
                    const int col = wn * 64 + nt * 8 + qp * 2;
                    float* d0 = &g_p[(m0 + rr) * 128 + col];
                    d0[0] = acc[mt][nt][0];
                    d0[1] = acc[mt][nt][1];
                    float* d1 = &g_p[(m0 + rr + 8) * 128 + col];
                    d1[0] = acc[mt][nt][2];
                    d1[1] = acc[mt][nt][3];
                }
            }
        } else {
            float wb[8][2];
#pragma unroll
            for (int nt = 0; nt < 8; nt++) {
                const int col = wn * 64 + nt * 8 + qp * 2;
                wb[nt][0] = g_W2bT[o * 512 + j0 + col];
                wb[nt][1] = g_W2bT[o * 512 + j0 + col + 1];
            }
            __syncthreads();
#pragma unroll
            for (int mt = 0; mt < 4; mt++) {
                const int rr = wm * 64 + mt * 16 + g;
#pragma unroll
                for (int nt = 0; nt < 8; nt++) {
                    const int col = wn * 64 + nt * 8 + qp * 2;
                    *(half2*)(smem + rr * 272 + col * 2) =
                        __floats2half2_rn(acc[mt][nt][0] + wb[nt][0], acc[mt][nt][1] + wb[nt][1]);
                    *(half2*)(smem + (rr + 8) * 272 + col * 2) =
                        __floats2half2_rn(acc[mt][nt][2] + wb[nt][0], acc[mt][nt][3] + wb[nt][1]);
                }
            }
            __syncthreads();
#pragma unroll
            for (int i = 0; i < 16; i++) {
                const int idx = t + i * 128;
                const int rr = idx >> 4, colq = idx & 15;
                uint4 v = *(uint4*)(smem + rr * 272 + colq * 16);
                *(uint4*)(g_Uhi + ((m0 + rr) * 128 + o) * 512 + j0 + colq * 8) = v;
            }
        }
        // release: all stores visible, then count this CTA
        __threadfence();
        __syncthreads();
        if (t == 0) atomicAdd(&g_cnt[grp], 1);
    } else {
        // ================= stage 2 =================
        const int s = r - 513;
        const int gx = s >> 1, n0 = (s & 1) * 128;
        const int row = grp * 128 + gx;            // global (b,x) index
        const int b = row >> 8, x = row & 255;

        // acquire: wait for this m-tile's 513 stage1 CTAs
        if (t == 0) {
            while (*(volatile int*)&g_cnt[grp] != 513) __nanosleep(64);
        }
        __syncthreads();
        __threadfence();

        const size_t a_row0 = (size_t)row * 128;        // U rows (o)
        const size_t b_row0 = (size_t)b * L_ + n0;      // in2 rows (y)

        mma_mainloop(smem, g_Uhi + a_row0 * 512, g_I2hi + b_row0 * 512, acc, wm, wn, lane, t);

        __shared__ float pb_s[128];
        __syncthreads();
        if (t < 128) pb_s[t] = g_p[(size_t)row * 128 + t] + w2[(size_t)1024 * 128 + t];
        __syncthreads();

        float* S = (float*)smem;
#pragma unroll
        for (int mt = 0; mt < 4; mt++) {
            const int o = wm * 64 + mt * 16 + g;
            const float pb0 = pb_s[o], pb1 = pb_s[o + 8];
#pragma unroll
            for (int nt = 0; nt < 8; nt++) {
                const int y = wn * 64 + nt * 8 + qp * 2;
                S[y * 132 + o]           = acc[mt][nt][0] + pb0;
                S[(y + 1) * 132 + o]     = acc[mt][nt][1] + pb0;
                S[y * 132 + o + 8]       = acc[mt][nt][2] + pb1;
                S[(y + 1) * 132 + o + 8] = acc[mt][nt][3] + pb1;
            }
        }
        __syncthreads();
#pragma unroll
        for (int i = 0; i < 32; i++) {
            const int task = t + i * 128;
            const int y = task >> 5, oq = task & 31;
            float4 v = *(float4*)&S[y * 132 + oq * 4];
            *(float4*)(out + (((size_t)b * L_ + x) * L_ + n0 + y) * 128 + oq * 4) = v;
        }
    }
}

// -------------------- unified prep kernel --------------------
// grid x layout (256 thr each):
//   [0, 16384)        w1 transpose+cvt: n-tile = bx & 2047, k-tile = bx >> 11
//   [16384, 17408)    cvt in1 -> g_Ahi
//   [17408, 18432)    cvt in2 -> g_I2hi
//   [18432, 18688)    w2 split -> g_W2aT (fp16) / g_W2bT (fp32)
//   [18688]           zero dependency counters
__global__ __launch_bounds__(256) void prep_kernel(const float* __restrict__ w1,
                                                   const float* __restrict__ in1,
                                                   const float* __restrict__ in2,
                                                   const float* __restrict__ w2) {
    const int bx = blockIdx.x, t = threadIdx.x;

    if (bx < 16384) {
        __shared__ float sm[64][33];
        const int n0 = (bx & 2047) * 32;
        const int k0 = (bx >> 11) * 64;
#pragma unroll
        for (int it = 0; it < 8; it++) {
            const int idx = t + it * 256;
            const int i = idx >> 5, j = idx & 31;
            sm[i][j] = w1[(size_t)(k0 + i) * 65536 + n0 + j];
        }
        __syncthreads();
        const int n = t >> 3, kq = t & 7;
        hf h[8];
#pragma unroll
        for (int u = 0; u < 8; u++) h[u] = __float2half_rn(sm[kq * 8 + u][n]);
        *(uint4*)(g_Whi + (size_t)(n0 + n) * 512 + k0 + kq * 8) = *(uint4*)h;
    } else if (bx < 18432) {
        const int which = (bx >= 17408);
        const int i = (bx - (which ? 17408 : 16384)) * 256 + t;   // float4 index
        const float* src = which ? in2 : in1;
        float4 v = ((const float4*)src)[i];
        half2 h0 = __floats2half2_rn(v.x, v.y);
        half2 h1 = __floats2half2_rn(v.z, v.w);
        hf* dh = which ? g_I2hi : g_Ahi;
        ((half2*)dh)[2 * i] = h0;
        ((half2*)dh)[2 * i + 1] = h1;
    } else if (bx < 18688) {
        const int idx = (bx - 18432) * 256 + t;   // 0..65535
        const int o = idx & 127, k = idx >> 7;    // coalesced reads over o
        const float a = w2[(size_t)k * 128 + o];
        const float b = w2[(size_t)(512 + k) * 128 + o];
        g_W2aT[o * 512 + k] = __float2half_rn(a);
        g_W2bT[o * 512 + k] = b;
    } else {
        if (t < 16) g_cnt[t] = 0;
    }
}

// -------------------- host --------------------
extern "C" void kernel_launch(void* const* d_in, const int* in_sizes, int n_in,
                              void* d_out, int out_size) {
    const float* in1 = (const float*)d_in[0];
    const float* in2 = (const float*)d_in[1];
    const float* w1  = (const float*)d_in[2];
    const float* w2  = (const float*)d_in[3];
    float* out = (float*)d_out;

    cudaFuncSetAttribute(fused_mma, cudaFuncAttributeMaxDynamicSharedMemorySize, SMEM_BYTES);

    prep_kernel<<<18689, 256>>>(w1, in1, in2, w2);
    fused_mma<<<16 * 769, 128, SMEM_BYTES>>>(w2, out);
}

// round 17
// speedup vs baseline: 1.1603x; 1.1603x over previous
#include <cuda_runtime.h>
#include <cuda_fp16.h>
#include <cstdint>
#include <cstddef>

// Biaffine: out[b,x,y,o] = sum_ij in1[b,x,i] w1[i,o,j] in2[b,y,j] + p + q + bias
//   stage1: U' = in1_hi @ w1_hi^T (+ w2b^T folded -> q) ; p-tile = in1 @ w2a
//   stage2: out = U' @ in2hi^T + (p + bias)
// ONE fused kernel; grid ordered with ONE-GROUP LAG so stage2(g) CTAs are
// dispatched only after stage1(g+1) — by residency-window arithmetic all of
// stage1(g) has finished before any stage2(g) CTA acquires an SM slot, so the
// dependency spin is cold. Counters (fence+atomicAdd / volatile spin) keep
// correctness regardless of scheduling.
// mma.sync.m16n8k16 fp16 fp32-acc at the sm_103a SIMT HMMA ceiling.

#define B_ 8
#define L_ 256
#define D_ 512
#define O_ 128
#define NCH 8                   // 512 / 64
#define TBUF 18432              // 128 rows * 144B
#define CBUF (2 * TBUF)         // A + B tiles per chunk buffer
#define SMEM_BYTES 110592       // 3 * CBUF (epilogues fit inside)

using hf = __half;

// -------------------- device globals (no runtime alloc) --------------------
__device__ __align__(128) hf g_Ahi[2048 * 512];
__device__ __align__(128) hf g_I2hi[2048 * 512];
__device__ __align__(128) hf g_Whi[(size_t)65536 * 512];
__device__ __align__(128) hf g_Uhi[(size_t)262144 * 512];
__device__ __align__(128) hf g_W2aT[128 * 512];     // [o][i] fp16 (p-tile B operand)
__device__ __align__(128) float g_W2bT[128 * 512];  // [o][j] fp32 (U epilogue addend)
__device__ __align__(128) float g_p[2048 * 128];
__device__ int g_cnt[16];                           // per-m-tile completion counters

// -------------------- helpers --------------------
__device__ __forceinline__ uint32_t smem_u32(const void* p) {
    uint32_t a;
    asm("{ .reg .u64 t; cvta.to.shared.u64 t, %1; cvt.u32.u64 %0, t; }" : "=r"(a) : "l"(p));
    return a;
}
__device__ __forceinline__ void cpa16(uint32_t s, const void* g) {
    asm volatile("cp.async.cg.shared.global [%0], [%1], 16;" :: "r"(s), "l"(g));
}
#define CP_COMMIT asm volatile("cp.async.commit_group;" ::: "memory")
#define CP_WAIT2  asm volatile("cp.async.wait_group 2;" ::: "memory")
#define CP_WAIT1  asm volatile("cp.async.wait_group 1;" ::: "memory")
#define CP_WAIT0  asm volatile("cp.async.wait_group 0;" ::: "memory")

__device__ __forceinline__ void ldmx4(uint32_t* r, uint32_t addr) {
    asm volatile("ldmatrix.sync.aligned.m8n8.x4.shared.b16 {%0,%1,%2,%3}, [%4];"
                 : "=r"(r[0]), "=r"(r[1]), "=r"(r[2]), "=r"(r[3]) : "r"(addr));
}
__device__ __forceinline__ void mma16816(float* c, const uint32_t* a, uint32_t b0, uint32_t b1) {
    asm("mma.sync.aligned.m16n8k16.row.col.f32.f16.f16.f32 "
        "{%0,%1,%2,%3},{%4,%5,%6,%7},{%8,%9},{%0,%1,%2,%3};"
        : "+f"(c[0]), "+f"(c[1]), "+f"(c[2]), "+f"(c[3])
        : "r"(a[0]), "r"(a[1]), "r"(a[2]), "r"(a[3]), "r"(b0), "r"(b1));
}

// -------------------- chunk loader: A + B tiles 128x64 fp16 (144B stride) ---
__device__ __forceinline__ void load2(uint32_t sbase, int buf,
                                      const hf* __restrict__ ta,
                                      const hf* __restrict__ tb,
                                      int kcol, int t) {
    const int r = t >> 3, c = t & 7;               // r 0..15, c 0..7 (16B units)
    const uint32_t so = sbase + buf * CBUF + r * 144 + c * 16;
    const size_t go = (size_t)r * 512 + kcol + c * 8;
    const hf* ga = ta + go;
    const hf* gb = tb + go;
#pragma unroll
    for (int p = 0; p < 8; p++) cpa16(so + p * (16 * 144), ga + (size_t)16 * p * 512);
#pragma unroll
    for (int p = 0; p < 8; p++) cpa16(so + TBUF + p * (16 * 144), gb + (size_t)16 * p * 512);
}

// -------------------- fragment load + mma --------------------
__device__ __forceinline__ void ld_frags(uint32_t sbase, int buf, int kst,
                                         int wm, int wn, uint32_t lro,
                                         uint32_t ar[4][4], uint32_t br[4][4]) {
    const uint32_t sA = sbase + buf * CBUF + wm * (64 * 144) + lro + kst * 32;
    const uint32_t sB = sbase + buf * CBUF + TBUF + wn * (64 * 144) + lro + kst * 32;
#pragma unroll
    for (int mt = 0; mt < 4; mt++) ldmx4(ar[mt], sA + mt * (16 * 144));
#pragma unroll
    for (int n2 = 0; n2 < 4; n2++) ldmx4(br[n2], sB + n2 * (16 * 144));
}
__device__ __forceinline__ void do_mma(float acc[4][8][4],
                                       uint32_t ar[4][4], uint32_t br[4][4]) {
#pragma unroll
    for (int mt = 0; mt < 4; mt++)
#pragma unroll
        for (int n2 = 0; n2 < 4; n2++) {
            mma16816(acc[mt][n2 * 2 + 0], ar[mt], br[n2][0], br[n2][2]);
            mma16816(acc[mt][n2 * 2 + 1], ar[mt], br[n2][1], br[n2][3]);
        }
}

// -------------------- shared mainloop (CTA 128x128, warps 2x2, 64x64) ------
__device__ __forceinline__ void mma_mainloop(char* smem,
                                             const hf* pa, const hf* pb,
                                             float acc[4][8][4],
                                             int wm, int wn, int lane, int t) {
    const uint32_t sbase = smem_u32(smem);
    const uint32_t lro = (lane & 15) * 144 + (lane >> 4) * 16;

    uint32_t a0[4][4], b0[4][4], a1[4][4], b1[4][4];

    load2(sbase, 0, pa, pb, 0, t);   CP_COMMIT;
    load2(sbase, 1, pa, pb, 64, t);  CP_COMMIT;
    load2(sbase, 2, pa, pb, 128, t); CP_COMMIT;
    CP_WAIT2;                 // buf0 complete
    __syncthreads();
    ld_frags(sbase, 0, 0, wm, wn, lro, a0, b0);

#pragma unroll
    for (int c = 0; c < NCH; c++) {
        const int buf = c % 3;
        ld_frags(sbase, buf, 1, wm, wn, lro, a1, b1);
        do_mma(acc, a0, b0);
        ld_frags(sbase, buf, 2, wm, wn, lro, a0, b0);
        do_mma(acc, a1, b1);
        ld_frags(sbase, buf, 3, wm, wn, lro, a1, b1);
        do_mma(acc, a0, b0);

        if (c + 1 < NCH) {
            if (c == NCH - 2) { CP_WAIT0; } else { CP_WAIT1; }
            __syncthreads();   // all warps done reading buf c
            ld_frags(sbase, (c + 1) % 3, 0, wm, wn, lro, a0, b0);
            do_mma(acc, a1, b1);
            if (c + 3 < NCH) { load2(sbase, (c + 3) % 3, pa, pb, (c + 3) * 64, t); CP_COMMIT; }
        } else {
            do_mma(acc, a1, b1);
        }
    }
}

// -------------------- fused kernel, one-group-lag ordering --------------------
// Grid (12304 CTAs): [s1 g0 (513)] then for q=0..14: [s1 g(q+1) (513)][s2 gq (256)]
// then [s2 g15 (256)].  s1: n-tile idx (512 = p-tile).  s2: idx = gx*2 + ytile.
__global__ __launch_bounds__(128, 2) void fused_mma(const float* __restrict__ w2,
                                                    float* __restrict__ out) {
    extern __shared__ char smem[];
    const int bid = blockIdx.x;
    int kind, grp, idx;
    if (bid < 513) {
        kind = 0; grp = 0; idx = bid;
    } else if (bid < 513 + 15 * 769) {
        const int q = (bid - 513) / 769;
        const int rr = (bid - 513) % 769;
        if (rr < 513) { kind = 0; grp = q + 1; idx = rr; }
        else          { kind = 1; grp = q;     idx = rr - 513; }
    } else {
        kind = 1; grp = 15; idx = bid - (513 + 15 * 769);
    }

    const int t = threadIdx.x, lane = t & 31, wid = t >> 5;
    const int wm = wid & 1, wn = wid >> 1;
    const int g = lane >> 2, qp = lane & 3;

    float acc[4][8][4];
#pragma unroll
    for (int i = 0; i < 4; i++)
#pragma unroll
        for (int j = 0; j < 8; j++)
#pragma unroll
            for (int k = 0; k < 4; k++) acc[i][j][k] = 0.f;

    if (kind == 0) {
        // ================= stage 1 =================
        const size_t m0 = (size_t)grp * 128;
        const bool ptile = (idx == 512);
        const int n0 = ptile ? 0 : idx * 128;
        const int o = n0 >> 9, j0 = n0 & 511;

        const hf* pb = ptile ? g_W2aT : (g_Whi + (size_t)n0 * 512);
        mma_mainloop(smem, g_Ahi + m0 * 512, pb, acc, wm, wn, lane, t);

        if (ptile) {
#pragma unroll
            for (int mt = 0; mt < 4; mt++) {
                const int rr = wm * 64 + mt * 16 + g;
#pragma unroll
                for (int nt = 0; nt < 8; nt++) {
                    const int col = wn * 64 + nt * 8 + qp * 2;
                    float* d0 = &g_p[(m0 + rr) * 128 + col];
                    d0[0] = acc[mt][nt][0];
                    d0[1] = acc[mt][nt][1];
                    float* d1 = &g_p[(m0 + rr + 8) * 128 + col];
                    d1[0] = acc[mt][nt][2];
                    d1[1] = acc[mt][nt][3];
                }
            }
        } else {
            float wb[8][2];
#pragma unroll
            for (int nt = 0; nt < 8; nt++) {
                const int col = wn * 64 + nt * 8 + qp * 2;
                wb[nt][0] = g_W2bT[o * 512 + j0 + col];
                wb[nt][1] = g_W2bT[o * 512 + j0 + col + 1];
            }
            __syncthreads();
#pragma unroll
            for (int mt = 0; mt < 4; mt++) {
                const int rr = wm * 64 + mt * 16 + g;
#pragma unroll
                for (int nt = 0; nt < 8; nt++) {
                    const int col = wn * 64 + nt * 8 + qp * 2;
                    *(half2*)(smem + rr * 272 + col * 2) =
                        __floats2half2_rn(acc[mt][nt][0] + wb[nt][0], acc[mt][nt][1] + wb[nt][1]);
                    *(half2*)(smem + (rr + 8) * 272 + col * 2) =
                        __floats2half2_rn(acc[mt][nt][2] + wb[nt][0], acc[mt][nt][3] + wb[nt][1]);
                }
            }
            __syncthreads();
#pragma unroll
            for (int i = 0; i < 16; i++) {
                const int ii = t + i * 128;
                const int rr = ii >> 4, colq = ii & 15;
                uint4 v = *(uint4*)(smem + rr * 272 + colq * 16);
                *(uint4*)(g_Uhi + ((m0 + rr) * 128 + o) * 512 + j0 + colq * 8) = v;
            }
        }
        // release: all stores visible, then count this CTA
        __threadfence();
        __syncthreads();
        if (t == 0) atomicAdd(&g_cnt[grp], 1);
    } else {
        // ================= stage 2 =================
        const int gx = idx >> 1, n0 = (idx & 1) * 128;
        const int row = grp * 128 + gx;            // global (b,x) index
        const int b = row >> 8, x = row & 255;

        // acquire: wait for this m-tile's 513 stage1 CTAs (cold path by ordering)
        if (t == 0) {
            while (*(volatile int*)&g_cnt[grp] != 513) __nanosleep(64);
        }
        __syncthreads();
        __threadfence();

        const size_t a_row0 = (size_t)row * 128;        // U rows (o)
        const size_t b_row0 = (size_t)b * L_ + n0;      // in2 rows (y)

        mma_mainloop(smem, g_Uhi + a_row0 * 512, g_I2hi + b_row0 * 512, acc, wm, wn, lane, t);

        __shared__ float pb_s[128];
        __syncthreads();
        if (t < 128) pb_s[t] = g_p[(size_t)row * 128 + t] + w2[(size_t)1024 * 128 + t];
        __syncthreads();

        float* S = (float*)smem;
#pragma unroll
        for (int mt = 0; mt < 4; mt++) {
            const int o = wm * 64 + mt * 16 + g;
            const float pb0 = pb_s[o], pb1 = pb_s[o + 8];
#pragma unroll
            for (int nt = 0; nt < 8; nt++) {
                const int y = wn * 64 + nt * 8 + qp * 2;
                S[y * 132 + o]           = acc[mt][nt][0] + pb0;
                S[(y + 1) * 132 + o]     = acc[mt][nt][1] + pb0;
                S[y * 132 + o + 8]       = acc[mt][nt][2] + pb1;
                S[(y + 1) * 132 + o + 8] = acc[mt][nt][3] + pb1;
            }
        }
        __syncthreads();
#pragma unroll
        for (int i = 0; i < 32; i++) {
            const int task = t + i * 128;
            const int y = task >> 5, oq = task & 31;
            float4 v = *(float4*)&S[y * 132 + oq * 4];
            *(float4*)(out + (((size_t)b * L_ + x) * L_ + n0 + y) * 128 + oq * 4) = v;
        }
    }
}

// -------------------- unified prep kernel --------------------
// grid x layout (256 thr each):
//   [0, 16384)        w1 transpose+cvt: n-tile = bx & 2047, k-tile = bx >> 11
//   [16384, 17408)    cvt in1 -> g_Ahi
//   [17408, 18432)    cvt in2 -> g_I2hi
//   [18432, 18688)    w2 split -> g_W2aT (fp16) / g_W2bT (fp32)
//   [18688]           zero dependency counters
__global__ __launch_bounds__(256) void prep_kernel(const float* __restrict__ w1,
                                                   const float* __restrict__ in1,
                                                   const float* __restrict__ in2,
                                                   const float* __restrict__ w2) {
    const int bx = blockIdx.x, t = threadIdx.x;

    if (bx < 16384) {
        __shared__ float sm[64][33];
        const int n0 = (bx & 2047) * 32;
        const int k0 = (bx >> 11) * 64;
#pragma unroll
        for (int it = 0; it < 8; it++) {
            const int idx = t + it * 256;
            const int i = idx >> 5, j = idx & 31;
            sm[i][j] = w1[(size_t)(k0 + i) * 65536 + n0 + j];
        }
        __syncthreads();
        const int n = t >> 3, kq = t & 7;
        hf h[8];
#pragma unroll
        for (int u = 0; u < 8; u++) h[u] = __float2half_rn(sm[kq * 8 + u][n]);
        *(uint4*)(g_Whi + (size_t)(n0 + n) * 512 + k0 + kq * 8) = *(uint4*)h;
    } else if (bx < 18432) {
        const int which = (bx >= 17408);
        const int i = (bx - (which ? 17408 : 16384)) * 256 + t;   // float4 index
        const float* src = which ? in2 : in1;
        float4 v = ((const float4*)src)[i];
        half2 h0 = __floats2half2_rn(v.x, v.y);
        half2 h1 = __floats2half2_rn(v.z, v.w);
        hf* dh = which ? g_I2hi : g_Ahi;
        ((half2*)dh)[2 * i] = h0;
        ((half2*)dh)[2 * i + 1] = h1;
    } else if (bx < 18688) {
        const int idx = (bx - 18432) * 256 + t;   // 0..65535
        const int o = idx & 127, k = idx >> 7;    // coalesced reads over o
        const float a = w2[(size_t)k * 128 + o];
        const float b = w2[(size_t)(512 + k) * 128 + o];
        g_W2aT[o * 512 + k] = __float2half_rn(a);
        g_W2bT[o * 512 + k] = b;
    } else {
        if (t < 16) g_cnt[t] = 0;
    }
}

// -------------------- host --------------------
extern "C" void kernel_launch(void* const* d_in, const int* in_sizes, int n_in,
                              void* d_out, int out_size) {
    const float* in1 = (const float*)d_in[0];
    const float* in2 = (const float*)d_in[1];
    const float* w1  = (const float*)d_in[2];
    const float* w2  = (const float*)d_in[3];
    float* out = (float*)d_out;

    cudaFuncSetAttribute(fused_mma, cudaFuncAttributeMaxDynamicSharedMemorySize, SMEM_BYTES);

    prep_kernel<<<18689, 256>>>(w1, in1, in2, w2);
    fused_mma<<<16 * 769, 128, SMEM_BYTES>>>(w2, out);
}